// round 10
// baseline (speedup 1.0000x reference)
#include <cuda_runtime.h>
#include <math.h>

#define BB 32
#define TT 256
#define IND 64
#define DD 128

// output layout (floats): h_final | y | jacs | dh_dWh
#define OUT_Y   ((size_t)BB * DD)                              // 4096
#define OUT_JAC (OUT_Y + (size_t)BB * TT * DD)                 // 1052672
#define OUT_DWH (OUT_JAC + (size_t)TT * BB * DD * DD)          // 135270400

// scratch (device globals; allocation-free rule)
__device__ float g_scr[TT * BB * DD];
__device__ float c_scr[TT * BB * DD];
__device__ float d_scr[TT * BB * DD];
__device__ int   flag_scr[TT * BB];
__device__ float c2_scr[BB * DD];
__device__ float d2_scr[BB * DD];

// ---------------- XLA:CPU math replicas ----------------
// XLA shared EmitErfF32: clamp [-4,4], erf(x) = x * P(x^2) / Q(x^2).
// Per-op mul/add (XLA:CPU default has fast-math OFF -> LLVM does NOT contract to fma).
__device__ __forceinline__ float erf_xla_cpu(float x) {
    float w  = fminf(fmaxf(x, -4.0f), 4.0f);
    float x2 = __fmul_rn(w, w);
    float p;
    p = __fadd_rn(__fmul_rn(x2, -2.72614225801306e-10f), 2.77068142495902e-08f);
    p = __fadd_rn(__fmul_rn(x2, p), -2.10102402082508e-06f);
    p = __fadd_rn(__fmul_rn(x2, p), -5.69250639462346e-05f);
    p = __fadd_rn(__fmul_rn(x2, p), -7.34990630326855e-04f);
    p = __fadd_rn(__fmul_rn(x2, p), -2.95459980854025e-03f);
    p = __fadd_rn(__fmul_rn(x2, p), -1.60960333262415e-02f);
    p = __fmul_rn(w, p);
    float q;
    q = __fadd_rn(__fmul_rn(x2, -1.45660718464996e-05f), -2.13374055278905e-04f);
    q = __fadd_rn(__fmul_rn(x2, q), -1.68282697438203e-03f);
    q = __fadd_rn(__fmul_rn(x2, q), -7.37332916720468e-03f);
    q = __fadd_rn(__fmul_rn(x2, q), -1.42647390514189e-02f);
    return __fdiv_rn(p, q);
}

// Correctly-rounded f32 exp (glibc expf is CR to <=0.5000002 ulp): compute in f64, round once.
__device__ __forceinline__ float exp_cr(float x) {
    return (float)exp((double)x);
}

// XLA logistic_expander (current): logistic(x) = 1 / (1 + exp(-x)), per-op.
__device__ __forceinline__ float sigmoid_xla_cpu(float s) {
    float e = exp_cr(__fmul_rn(s, -1.0f) * 1.0f);   // negate then exp
    return __fdiv_rn(1.0f, __fadd_rn(1.0f, e));
}

// ---------------- Phase 1: sequential recurrence, XLA:CPU bit replication ----------------
// One block per batch, 128 threads; thread i owns output element i.
// Dots: single-accumulator ascending-k fma chains (Eigen gebp order).
// gelu: a = (pre * (erf(pre / sqrt2) + 1)) / 2  (poly erf, jax op order, per-op).
// sigmoid: exp-form with CR exp.
// h-update: per-op rnd(rnd(g*h) + rnd(1-g)) (no contraction).
// smem: Wxs[64][128] | Whs[128][128] | Wgs[128][128] | hs[128] as[128] xs[64]
#define P1_SMEM_FLOATS (IND * DD + 2 * DD * DD + DD + DD + IND)
#define P1_SMEM_BYTES  (P1_SMEM_FLOATS * 4)

__global__ void __launch_bounds__(128)
phase1_kernel(const float* __restrict__ x, const float* __restrict__ h0,
              const float* __restrict__ Wx, const float* __restrict__ Wg,
              const float* __restrict__ Wh, float* __restrict__ out)
{
    extern __shared__ float sm[];
    float* Wxs = sm;                       // [k][i] row-major, as in gmem
    float* Whs = Wxs + IND * DD;           // [k][i]
    float* Wgs = Whs + DD * DD;            // [k][i]
    float* hs  = Wgs + DD * DD;            // [128]
    float* as_ = hs + DD;                  // [128]
    float* xs  = as_ + DD;                 // [64]

    const int b = blockIdx.x;
    const int i = threadIdx.x;             // 128 threads

    for (int idx = i; idx < IND * DD; idx += 128) Wxs[idx] = Wx[idx];
    for (int idx = i; idx < DD * DD; idx += 128) {
        Whs[idx] = Wh[idx];
        Wgs[idx] = Wg[idx];
    }
    hs[i] = h0[b * DD + i];
    __syncthreads();

    const float* xrow = x + (size_t)b * TT * IND;
    float* yrow = out + OUT_Y + (size_t)b * TT * DD;

    const float SQRT2   = 1.41421356237309515f;   // f32(np.sqrt(2)) = 0x3FB504F3
    const float INVSQ2P = 0.3989422804014327f;    // 1/sqrt(2*pi) (smooth dd only)

    for (int t = 0; t < TT; t++) {
        if (i < IND) xs[i] = xrow[t * IND + i];
        __syncthreads();                           // xs + hs ready

        // pre = (ascending chain x@Wx) + (ascending chain h@Wh)
        float acc1 = 0.0f, acc2 = 0.0f;
        #pragma unroll
        for (int k = 0; k < IND; k++)
            acc1 = fmaf(xs[k], Wxs[k * DD + i], acc1);
        #pragma unroll
        for (int k = 0; k < DD; k++)
            acc2 = fmaf(hs[k], Whs[k * DD + i], acc2);
        float pre = __fadd_rn(acc1, acc2);

        // gelu, jax op order: x * (erf(x / sqrt2) + 1) / 2, poly erf, per-op
        float u  = __fdiv_rn(pre, SQRT2);
        float er = erf_xla_cpu(u);
        float a  = __fdiv_rn(__fmul_rn(pre, __fadd_rn(er, 1.0f)), 2.0f);

        // gelu' (smooth accuracy only, feeds jac)
        float cdf = 0.5f * (1.0f + er);
        float dd  = cdf + pre * INVSQ2P * expf(-0.5f * pre * pre);

        as_[i] = a;
        __syncthreads();                           // as ready

        // s = ascending chain a @ Wgate
        float acc3 = 0.0f;
        #pragma unroll
        for (int k = 0; k < DD; k++)
            acc3 = fmaf(as_[k], Wgs[k * DD + i], acc3);

        float g = sigmoid_xla_cpu(acc3);
        float h = hs[i];
        float c = (h - 1.0f) * g * (1.0f - g);
        // per-op h-update: rnd(rnd(g*h) + rnd(1-g)) (no fast-math contraction)
        float hn = __fadd_rn(__fmul_rn(g, h), __fsub_rn(1.0f, g));

        size_t o = ((size_t)t * BB + b) * DD + i;
        g_scr[o] = g;
        c_scr[o] = c;
        d_scr[o] = dd;
        yrow[t * DD + i] = hn;

        int allz = __syncthreads_and(c == 0.0f);
        if (i == 0) flag_scr[t * BB + b] = allz;
        hs[i] = hn;
        // next iteration's first barrier protects hs
        __syncthreads();
    }

    // h_final
    out[b * DD + i] = hs[i];

    // extra eval for dh_dWh: pre' = x_last@Wx + h_final@Wh (xs still = x[:,T-1])
    {
        float acc1 = 0.0f, acc2 = 0.0f;
        #pragma unroll
        for (int k = 0; k < IND; k++)
            acc1 = fmaf(xs[k], Wxs[k * DD + i], acc1);
        #pragma unroll
        for (int k = 0; k < DD; k++)
            acc2 = fmaf(hs[k], Whs[k * DD + i], acc2);
        float pre = __fadd_rn(acc1, acc2);

        float u  = __fdiv_rn(pre, SQRT2);
        float er = erf_xla_cpu(u);
        float a  = __fdiv_rn(__fmul_rn(pre, __fadd_rn(er, 1.0f)), 2.0f);
        float cdf = 0.5f * (1.0f + er);
        d2_scr[b * DD + i] = cdf + pre * INVSQ2P * expf(-0.5f * pre * pre);

        as_[i] = a;
        __syncthreads();

        float acc3 = 0.0f;
        #pragma unroll
        for (int k = 0; k < DD; k++)
            acc3 = fmaf(as_[k], Wgs[k * DD + i], acc3);

        float g = sigmoid_xla_cpu(acc3);
        float h = hs[i];
        c2_scr[b * DD + i] = (h - 1.0f) * g * (1.0f - g);
    }
}

// ---------------- Phase 2: jacs = g*I + diag(c) * (diag(d)Wg)^T Wh^T  per (t,b) ----------------
// smem: Wgs[128*128] | WhT[128*128] | ds[128] cs[128] gs[128]
#define P2_SMEM_FLOATS (2 * DD * DD + 3 * DD)
#define P2_SMEM_BYTES  (P2_SMEM_FLOATS * 4)

__global__ void __launch_bounds__(256)
phase2_kernel(const float* __restrict__ Wg, const float* __restrict__ Wh,
              float* __restrict__ out)
{
    extern __shared__ float sm[];
    float* Wgs = sm;                 // [k][i]
    float* WhT = sm + DD * DD;       // [k][j] = Wh[j][k]
    float* ds  = WhT + DD * DD;
    float* cs  = ds + DD;
    float* gs  = cs + DD;

    const int tid = threadIdx.x;     // 256
    for (int idx = tid; idx < DD * DD; idx += 256) Wgs[idx] = Wg[idx];
    for (int idx = tid; idx < DD * DD; idx += 256) {
        int j = idx / DD, k = idx % DD;
        WhT[k * DD + j] = Wh[idx];
    }
    __syncthreads();

    const int ti = tid & 15, tj = tid >> 4;
    const int i0 = ti * 8, j0 = tj * 8;
    float* jbase = out + OUT_JAC;

    for (int job = blockIdx.x; job < TT * BB; job += gridDim.x) {
        float* jac = jbase + (size_t)job * (DD * DD);
        if (flag_scr[job]) {
            // all c == 0.0f exactly (h == 1) -> jac = diag(g) bit-identically
            const float* gj = g_scr + (size_t)job * DD;
            float4* j4 = (float4*)jac;
            #pragma unroll 4
            for (int idx = tid; idx < DD * DD / 4; idx += 256) {
                int row = idx >> 5;
                int c0  = (idx & 31) << 2;
                float gv = gj[row];
                float4 v;
                v.x = (row == c0 + 0) ? gv : 0.f;
                v.y = (row == c0 + 1) ? gv : 0.f;
                v.z = (row == c0 + 2) ? gv : 0.f;
                v.w = (row == c0 + 3) ? gv : 0.f;
                j4[idx] = v;
            }
        } else {
            if (tid < DD) {
                size_t o = (size_t)job * DD + tid;
                ds[tid] = d_scr[o];
                cs[tid] = c_scr[o];
                gs[tid] = g_scr[o];
            }
            __syncthreads();

            float acc[8][8];
            #pragma unroll
            for (int a = 0; a < 8; a++)
                #pragma unroll
                for (int q = 0; q < 8; q++) acc[a][q] = 0.f;

            #pragma unroll 2
            for (int k = 0; k < DD; k++) {
                float dk = ds[k];
                float4 wa0 = *(const float4*)(Wgs + k * DD + i0);
                float4 wa1 = *(const float4*)(Wgs + k * DD + i0 + 4);
                float4 wb0 = *(const float4*)(WhT + k * DD + j0);
                float4 wb1 = *(const float4*)(WhT + k * DD + j0 + 4);
                float av[8] = {wa0.x * dk, wa0.y * dk, wa0.z * dk, wa0.w * dk,
                               wa1.x * dk, wa1.y * dk, wa1.z * dk, wa1.w * dk};
                float bv[8] = {wb0.x, wb0.y, wb0.z, wb0.w, wb1.x, wb1.y, wb1.z, wb1.w};
                #pragma unroll
                for (int a = 0; a < 8; a++)
                    #pragma unroll
                    for (int q = 0; q < 8; q++)
                        acc[a][q] = fmaf(av[a], bv[q], acc[a][q]);
            }

            #pragma unroll
            for (int a = 0; a < 8; a++) {
                int irow = i0 + a;
                float ci = cs[irow], gi = gs[irow];
                float v[8];
                #pragma unroll
                for (int q = 0; q < 8; q++) {
                    float val = ci * acc[a][q];
                    if (irow == j0 + q) val += gi;
                    v[q] = val;
                }
                float* dst = jac + (size_t)irow * DD + j0;
                *(float4*)(dst)     = make_float4(v[0], v[1], v[2], v[3]);
                *(float4*)(dst + 4) = make_float4(v[4], v[5], v[6], v[7]);
            }
            __syncthreads();   // protect ds/cs/gs before next job
        }
    }
}

// ---------------- Phase 3: dh_dWh[b,i,p,q] = c2_i * h_p * d2_q * Wg[q,i] ----------------
__global__ void __launch_bounds__(256)
phase3_kernel(const float* __restrict__ Wg, float* __restrict__ out)
{
    __shared__ float vs[DD];
    __shared__ float hsh[DD];
    const int bi = blockIdx.x;          // b*128 + i
    const int b = bi >> 7, i = bi & 127;
    const int tid = threadIdx.x;        // 256

    if (tid < DD) {
        float c2 = c2_scr[b * DD + i];
        vs[tid]  = c2 * d2_scr[b * DD + tid] * Wg[tid * DD + i];
        hsh[tid] = out[b * DD + tid];   // h_final (phase1 wrote it)
    }
    __syncthreads();

    float4* dst = (float4*)(out + OUT_DWH + (size_t)bi * DD * DD);
    const float4* vs4 = (const float4*)vs;
    #pragma unroll 4
    for (int idx = tid; idx < DD * DD / 4; idx += 256) {
        int p  = idx >> 5;
        int q4 = idx & 31;
        float hp = hsh[p];
        float4 v = vs4[q4];
        dst[idx] = make_float4(v.x * hp, v.y * hp, v.z * hp, v.w * hp);
    }
}

extern "C" void kernel_launch(void* const* d_in, const int* in_sizes, int n_in,
                              void* d_out, int out_size) {
    const float* x  = (const float*)d_in[0];
    const float* h0 = (const float*)d_in[1];
    const float* Wx = (const float*)d_in[2];
    const float* Wg = (const float*)d_in[3];
    const float* Wh = (const float*)d_in[4];
    float* out = (float*)d_out;

    cudaFuncSetAttribute(phase1_kernel, cudaFuncAttributeMaxDynamicSharedMemorySize, P1_SMEM_BYTES);
    cudaFuncSetAttribute(phase2_kernel, cudaFuncAttributeMaxDynamicSharedMemorySize, P2_SMEM_BYTES);

    phase1_kernel<<<BB, 128, P1_SMEM_BYTES>>>(x, h0, Wx, Wg, Wh, out);
    phase2_kernel<<<152, 256, P2_SMEM_BYTES>>>(Wg, Wh, out);
    phase3_kernel<<<BB * DD, 256>>>(Wg, out);
}

// round 11
// speedup vs baseline: 2.1099x; 2.1099x over previous
#include <cuda_runtime.h>
#include <math.h>

#define BB 32
#define TT 256
#define IND 64
#define DD 128

// output layout (floats): h_final | y | jacs | dh_dWh
#define OUT_Y   ((size_t)BB * DD)                              // 4096
#define OUT_JAC (OUT_Y + (size_t)BB * TT * DD)                 // 1052672
#define OUT_DWH (OUT_JAC + (size_t)TT * BB * DD * DD)          // 135270400

// scratch (device globals; allocation-free rule)
__device__ float g_scr[TT * BB * DD];
__device__ float c_scr[TT * BB * DD];
__device__ float p_scr[TT * BB * DD];       // pre activations (dd computed in phase2)
__device__ float pre1_scr[(size_t)BB * TT * DD];  // x @ Wx, precomputed
__device__ float c2_scr[BB * DD];
__device__ float d2_scr[BB * DD];

// ---------------- XLA:CPU math replicas (bit-exact path — DO NOT TOUCH) ----------------
// XLA shared EmitErfF32: clamp [-4,4], erf(x) = x * P(x^2) / Q(x^2), per-op mul/add.
__device__ __forceinline__ float erf_xla_cpu(float x) {
    float w  = fminf(fmaxf(x, -4.0f), 4.0f);
    float x2 = __fmul_rn(w, w);
    float p;
    p = __fadd_rn(__fmul_rn(x2, -2.72614225801306e-10f), 2.77068142495902e-08f);
    p = __fadd_rn(__fmul_rn(x2, p), -2.10102402082508e-06f);
    p = __fadd_rn(__fmul_rn(x2, p), -5.69250639462346e-05f);
    p = __fadd_rn(__fmul_rn(x2, p), -7.34990630326855e-04f);
    p = __fadd_rn(__fmul_rn(x2, p), -2.95459980854025e-03f);
    p = __fadd_rn(__fmul_rn(x2, p), -1.60960333262415e-02f);
    p = __fmul_rn(w, p);
    float q;
    q = __fadd_rn(__fmul_rn(x2, -1.45660718464996e-05f), -2.13374055278905e-04f);
    q = __fadd_rn(__fmul_rn(x2, q), -1.68282697438203e-03f);
    q = __fadd_rn(__fmul_rn(x2, q), -7.37332916720468e-03f);
    q = __fadd_rn(__fmul_rn(x2, q), -1.42647390514189e-02f);
    return __fdiv_rn(p, q);
}

// Correctly-rounded f32 exp: compute in f64, round once (matches glibc expf).
__device__ __forceinline__ float exp_cr(float x) {
    return (float)exp((double)x);
}

// XLA logistic_expander: logistic(x) = 1 / (1 + exp(-x)), per-op.
__device__ __forceinline__ float sigmoid_xla_cpu(float s) {
    float e = exp_cr(__fmul_rn(s, -1.0f));
    return __fdiv_rn(1.0f, __fadd_rn(1.0f, e));
}

// ---------------- Phase 0: pre1[b,t,i] = ascending-chain x[b,t,:] @ Wx[:,i] ----------------
__global__ void __launch_bounds__(128)
phase0_kernel(const float* __restrict__ x, const float* __restrict__ Wx)
{
    __shared__ float xs[IND];
    const int t = blockIdx.x, b = blockIdx.y, i = threadIdx.x;
    if (i < IND) xs[i] = x[((size_t)b * TT + t) * IND + i];
    __syncthreads();
    float acc = 0.0f;
    #pragma unroll
    for (int kb = 0; kb < IND; kb += 8) {
        float w[8];
        #pragma unroll
        for (int u = 0; u < 8; u++) w[u] = Wx[(kb + u) * DD + i];
        #pragma unroll
        for (int u = 0; u < 8; u++) acc = fmaf(xs[kb + u], w[u], acc);
    }
    pre1_scr[((size_t)b * TT + t) * DD + i] = acc;
}

// ---------------- Phase 1: sequential recurrence (bit-exact XLA:CPU) ----------------
// One block per batch, 128 threads; thread i owns output element i.
// smem: Whs[128][128] | Wgs[128][128] | hs[128] | as[128]
#define P1_SMEM_FLOATS (2 * DD * DD + DD + DD)
#define P1_SMEM_BYTES  (P1_SMEM_FLOATS * 4)

__global__ void __launch_bounds__(128, 1)
phase1_kernel(const float* __restrict__ h0, const float* __restrict__ Wg,
              const float* __restrict__ Wh, float* __restrict__ out)
{
    extern __shared__ float sm[];
    float* Whs = sm;                       // [k][i]
    float* Wgs = Whs + DD * DD;            // [k][i]
    float* hs  = Wgs + DD * DD;            // [128]
    float* as_ = hs + DD;                  // [128]

    const int b = blockIdx.x;
    const int i = threadIdx.x;             // 128 threads

    for (int idx = i; idx < DD * DD; idx += 128) {
        Whs[idx] = Wh[idx];
        Wgs[idx] = Wg[idx];
    }
    hs[i] = h0[b * DD + i];
    __syncthreads();

    const float* p1 = pre1_scr + (size_t)b * TT * DD + i;
    float* yrow = out + OUT_Y + (size_t)b * TT * DD;

    const float SQRT2 = 1.41421356237309515f;   // f32(np.sqrt(2))

    float preP = p1[0];
    for (int t = 0; t < TT; t++) {
        float nextP = (t + 1 < TT) ? p1[(size_t)(t + 1) * DD] : 0.0f;

        // acc2 = ascending chain h @ Wh (batched loads, serial fma chain)
        float acc2 = 0.0f;
        #pragma unroll
        for (int kb = 0; kb < DD; kb += 8) {
            float w[8], hv[8];
            #pragma unroll
            for (int u = 0; u < 8; u++) { w[u] = Whs[(kb + u) * DD + i]; hv[u] = hs[kb + u]; }
            #pragma unroll
            for (int u = 0; u < 8; u++) acc2 = fmaf(hv[u], w[u], acc2);
        }
        float pre = __fadd_rn(preP, acc2);

        // gelu, jax op order: x * (erf(x / sqrt2) + 1) / 2, poly erf, per-op
        float u_  = __fdiv_rn(pre, SQRT2);
        float er  = erf_xla_cpu(u_);
        float a   = __fdiv_rn(__fmul_rn(pre, __fadd_rn(er, 1.0f)), 2.0f);

        as_[i] = a;
        __syncthreads();                   // as ready; all hs reads (acc2) done

        // acc3 = ascending chain a @ Wgate
        float acc3 = 0.0f;
        #pragma unroll
        for (int kb = 0; kb < DD; kb += 8) {
            float w[8], av[8];
            #pragma unroll
            for (int u = 0; u < 8; u++) { w[u] = Wgs[(kb + u) * DD + i]; av[u] = as_[kb + u]; }
            #pragma unroll
            for (int u = 0; u < 8; u++) acc3 = fmaf(av[u], w[u], acc3);
        }

        float g = sigmoid_xla_cpu(acc3);
        float h = hs[i];
        float c = (h - 1.0f) * g * (1.0f - g);
        // per-op h-update: rnd(rnd(g*h) + rnd(1-g))
        float hn = __fadd_rn(__fmul_rn(g, h), __fsub_rn(1.0f, g));

        size_t o = ((size_t)t * BB + b) * DD + i;
        g_scr[o] = g;
        c_scr[o] = c;
        p_scr[o] = pre;
        yrow[(size_t)t * DD + i] = hn;
        hs[i] = hn;
        __syncthreads();                   // hs published for next acc2
        preP = nextP;
    }

    // h_final
    out[b * DD + i] = hs[i];

    // extra eval for dh_dWh: pre' = pre1[T-1] + h_final@Wh
    {
        float acc1 = p1[(size_t)(TT - 1) * DD];
        float acc2 = 0.0f;
        #pragma unroll
        for (int kb = 0; kb < DD; kb += 8) {
            float w[8], hv[8];
            #pragma unroll
            for (int u = 0; u < 8; u++) { w[u] = Whs[(kb + u) * DD + i]; hv[u] = hs[kb + u]; }
            #pragma unroll
            for (int u = 0; u < 8; u++) acc2 = fmaf(hv[u], w[u], acc2);
        }
        float pre = __fadd_rn(acc1, acc2);

        float u_ = __fdiv_rn(pre, SQRT2);
        float er = erf_xla_cpu(u_);
        float a  = __fdiv_rn(__fmul_rn(pre, __fadd_rn(er, 1.0f)), 2.0f);
        float cdf = 0.5f * (1.0f + er);
        d2_scr[b * DD + i] = cdf + pre * 0.3989422804014327f * expf(-0.5f * pre * pre);

        as_[i] = a;
        __syncthreads();

        float acc3 = 0.0f;
        #pragma unroll
        for (int kb = 0; kb < DD; kb += 8) {
            float w[8], av[8];
            #pragma unroll
            for (int u = 0; u < 8; u++) { w[u] = Wgs[(kb + u) * DD + i]; av[u] = as_[kb + u]; }
            #pragma unroll
            for (int u = 0; u < 8; u++) acc3 = fmaf(av[u], w[u], acc3);
        }

        float g = sigmoid_xla_cpu(acc3);
        float h = hs[i];
        c2_scr[b * DD + i] = (h - 1.0f) * g * (1.0f - g);
    }
}

// ---------------- Phase 2: jacs, per-row sparsity ----------------
// jac[i,j] = g_i d_ij + c_i * sum_k dd_k Wg[k,i] Wh[j,k];  row is g_i*e_i when c_i == 0.
// smem: Wgs[128*128] | WhT[128*128] | ds[128] cs[128] gs[128] | rowlist[128]
#define P2_SMEM_FLOATS (2 * DD * DD + 3 * DD + DD)
#define P2_SMEM_BYTES  (P2_SMEM_FLOATS * 4)
#define P2_THRESH 64

__global__ void __launch_bounds__(256)
phase2_kernel(const float* __restrict__ Wg, const float* __restrict__ Wh,
              float* __restrict__ out)
{
    extern __shared__ float sm[];
    float* Wgs = sm;                 // [k][i]
    float* WhT = sm + DD * DD;       // [k][j] = Wh[j][k]
    float* ds  = WhT + DD * DD;      // dd (gelu')
    float* cs  = ds + DD;
    float* gs  = cs + DD;
    int* rowlist = (int*)(gs + DD);
    __shared__ int cnt;

    const int tid = threadIdx.x;     // 256
    for (int idx = tid; idx < DD * DD; idx += 256) Wgs[idx] = Wg[idx];
    for (int idx = tid; idx < DD * DD; idx += 256) {
        int j = idx / DD, k = idx % DD;
        WhT[k * DD + j] = Wh[idx];
    }

    const int ti = tid & 15, tj = tid >> 4;
    const int i0 = ti * 8, j0 = tj * 8;
    float* jbase = out + OUT_JAC;

    for (int job = blockIdx.x; job < TT * BB; job += gridDim.x) {
        if (tid == 0) cnt = 0;
        __syncthreads();             // also protects ds/cs/gs/rowlist from prev job
        if (tid < DD) {
            size_t o = (size_t)job * DD + tid;
            float pre = p_scr[o];
            float cdf = 0.5f * (1.0f + erff(pre * 0.7071067811865476f));
            ds[tid] = cdf + pre * 0.3989422804014327f * expf(-0.5f * pre * pre);
            float c = c_scr[o];
            cs[tid] = c;
            gs[tid] = g_scr[o];
            if (c != 0.0f) { int p = atomicAdd(&cnt, 1); rowlist[p] = tid; }
        }
        __syncthreads();
        int n = cnt;
        float* jac = jbase + (size_t)job * (DD * DD);

        if (n > P2_THRESH) {
            // dense 8x8 register-tile GEMM
            float acc[8][8];
            #pragma unroll
            for (int a = 0; a < 8; a++)
                #pragma unroll
                for (int q = 0; q < 8; q++) acc[a][q] = 0.f;

            #pragma unroll 2
            for (int k = 0; k < DD; k++) {
                float dk = ds[k];
                float4 wa0 = *(const float4*)(Wgs + k * DD + i0);
                float4 wa1 = *(const float4*)(Wgs + k * DD + i0 + 4);
                float4 wb0 = *(const float4*)(WhT + k * DD + j0);
                float4 wb1 = *(const float4*)(WhT + k * DD + j0 + 4);
                float av[8] = {wa0.x * dk, wa0.y * dk, wa0.z * dk, wa0.w * dk,
                               wa1.x * dk, wa1.y * dk, wa1.z * dk, wa1.w * dk};
                float bv[8] = {wb0.x, wb0.y, wb0.z, wb0.w, wb1.x, wb1.y, wb1.z, wb1.w};
                #pragma unroll
                for (int a = 0; a < 8; a++)
                    #pragma unroll
                    for (int q = 0; q < 8; q++)
                        acc[a][q] = fmaf(av[a], bv[q], acc[a][q]);
            }

            #pragma unroll
            for (int a = 0; a < 8; a++) {
                int irow = i0 + a;
                float ci = cs[irow], gi = gs[irow];
                float v[8];
                #pragma unroll
                for (int q = 0; q < 8; q++) {
                    float val = ci * acc[a][q];
                    if (irow == j0 + q) val += gi;
                    v[q] = val;
                }
                float* dst = jac + (size_t)irow * DD + j0;
                *(float4*)(dst)     = make_float4(v[0], v[1], v[2], v[3]);
                *(float4*)(dst + 4) = make_float4(v[4], v[5], v[6], v[7]);
            }
        } else {
            // diag fill for inactive rows (c == 0 -> row = g_i * e_i exactly)
            float4* j4 = (float4*)jac;
            #pragma unroll 4
            for (int idx = tid; idx < DD * DD / 4; idx += 256) {
                int row = idx >> 5;
                if (cs[row] == 0.0f) {
                    int c0 = (idx & 31) << 2;
                    float gv = gs[row];
                    float4 v;
                    v.x = (row == c0 + 0) ? gv : 0.f;
                    v.y = (row == c0 + 1) ? gv : 0.f;
                    v.z = (row == c0 + 2) ? gv : 0.f;
                    v.w = (row == c0 + 3) ? gv : 0.f;
                    j4[idx] = v;
                }
            }
            // active rows: 2 rows per pass (threads 0-127 -> row r, 128-255 -> row r+1)
            for (int r = 0; r < n; r += 2) {
                int rr = r + (tid >> 7);
                if (rr < n) {
                    int irow = rowlist[rr];
                    int j = tid & 127;
                    float a0 = 0.f, a1 = 0.f;
                    #pragma unroll 4
                    for (int k = 0; k < DD; k += 2) {
                        a0 = fmaf(ds[k]     * Wgs[k * DD + irow],       WhT[k * DD + j],       a0);
                        a1 = fmaf(ds[k + 1] * Wgs[(k + 1) * DD + irow], WhT[(k + 1) * DD + j], a1);
                    }
                    float val = cs[irow] * (a0 + a1);
                    if (irow == j) val += gs[irow];
                    jac[(size_t)irow * DD + j] = val;
                }
            }
        }
    }
}

// ---------------- Phase 3: dh_dWh[b,i,p,q] = c2_i * h_p * d2_q * Wg[q,i] ----------------
__global__ void __launch_bounds__(256)
phase3_kernel(const float* __restrict__ Wg, float* __restrict__ out)
{
    __shared__ float vs[DD];
    __shared__ float hsh[DD];
    const int bi = blockIdx.x;          // b*128 + i
    const int b = bi >> 7, i = bi & 127;
    const int tid = threadIdx.x;        // 256

    if (tid < DD) {
        float c2 = c2_scr[b * DD + i];
        vs[tid]  = c2 * d2_scr[b * DD + tid] * Wg[tid * DD + i];
        hsh[tid] = out[b * DD + tid];   // h_final (phase1 wrote it)
    }
    __syncthreads();

    float4* dst = (float4*)(out + OUT_DWH + (size_t)bi * DD * DD);
    const float4* vs4 = (const float4*)vs;
    #pragma unroll 4
    for (int idx = tid; idx < DD * DD / 4; idx += 256) {
        int p  = idx >> 5;
        int q4 = idx & 31;
        float hp = hsh[p];
        float4 v = vs4[q4];
        dst[idx] = make_float4(v.x * hp, v.y * hp, v.z * hp, v.w * hp);
    }
}

extern "C" void kernel_launch(void* const* d_in, const int* in_sizes, int n_in,
                              void* d_out, int out_size) {
    const float* x  = (const float*)d_in[0];
    const float* h0 = (const float*)d_in[1];
    const float* Wx = (const float*)d_in[2];
    const float* Wg = (const float*)d_in[3];
    const float* Wh = (const float*)d_in[4];
    float* out = (float*)d_out;

    cudaFuncSetAttribute(phase1_kernel, cudaFuncAttributeMaxDynamicSharedMemorySize, P1_SMEM_BYTES);
    cudaFuncSetAttribute(phase2_kernel, cudaFuncAttributeMaxDynamicSharedMemorySize, P2_SMEM_BYTES);

    dim3 g0(TT, BB);
    phase0_kernel<<<g0, 128>>>(x, Wx);
    phase1_kernel<<<BB, 128, P1_SMEM_BYTES>>>(h0, Wg, Wh, out);
    phase2_kernel<<<148, 256, P2_SMEM_BYTES>>>(Wg, Wh, out);
    phase3_kernel<<<BB * DD, 256>>>(Wg, out);
}

// round 12
// speedup vs baseline: 2.5841x; 1.2248x over previous
#include <cuda_runtime.h>
#include <math.h>

#define BB 32
#define TT 256
#define IND 64
#define DD 128

#define NSM   148
#define NPROD 32
#define NCONS (NSM - NPROD)

// output layout (floats): h_final | y | jacs | dh_dWh
#define OUT_Y   ((size_t)BB * DD)                              // 4096
#define OUT_JAC (OUT_Y + (size_t)BB * TT * DD)                 // 1052672
#define OUT_DWH (OUT_JAC + (size_t)TT * BB * DD * DD)          // 135270400

// scratch (device globals; allocation-free rule)
__device__ float g_scr[TT * BB * DD];
__device__ float c_scr[TT * BB * DD];
__device__ float p_scr[TT * BB * DD];             // pre activations
__device__ float pre1_scr[(size_t)BB * TT * DD];  // x @ Wx, precomputed
__device__ float c2_scr[BB * DD];
__device__ float d2_scr[BB * DD];
__device__ volatile int progress[BB];             // steps completed per batch
__device__ int p1done_cnt;                        // producers finished

// ---------------- XLA:CPU math replicas (bit-exact path — DO NOT TOUCH) ----------------
__device__ __forceinline__ float erf_xla_cpu(float x) {
    float w  = fminf(fmaxf(x, -4.0f), 4.0f);
    float x2 = __fmul_rn(w, w);
    float p;
    p = __fadd_rn(__fmul_rn(x2, -2.72614225801306e-10f), 2.77068142495902e-08f);
    p = __fadd_rn(__fmul_rn(x2, p), -2.10102402082508e-06f);
    p = __fadd_rn(__fmul_rn(x2, p), -5.69250639462346e-05f);
    p = __fadd_rn(__fmul_rn(x2, p), -7.34990630326855e-04f);
    p = __fadd_rn(__fmul_rn(x2, p), -2.95459980854025e-03f);
    p = __fadd_rn(__fmul_rn(x2, p), -1.60960333262415e-02f);
    p = __fmul_rn(w, p);
    float q;
    q = __fadd_rn(__fmul_rn(x2, -1.45660718464996e-05f), -2.13374055278905e-04f);
    q = __fadd_rn(__fmul_rn(x2, q), -1.68282697438203e-03f);
    q = __fadd_rn(__fmul_rn(x2, q), -7.37332916720468e-03f);
    q = __fadd_rn(__fmul_rn(x2, q), -1.42647390514189e-02f);
    return __fdiv_rn(p, q);
}

__device__ __forceinline__ float exp_cr(float x) {
    return (float)exp((double)x);
}

__device__ __forceinline__ float sigmoid_xla_cpu(float s) {
    float e = exp_cr(__fmul_rn(s, -1.0f));
    return __fdiv_rn(1.0f, __fadd_rn(1.0f, e));
}

// ---------------- Phase 0: pre1 = x @ Wx (ascending chain) + flag reset ----------------
__global__ void __launch_bounds__(128)
phase0_kernel(const float* __restrict__ x, const float* __restrict__ Wx)
{
    __shared__ float xs[IND];
    const int t = blockIdx.x, b = blockIdx.y, i = threadIdx.x;
    if (t == 0 && b == 0) {                 // reset sync state for this replay
        if (i < BB) progress[i] = 0;
        if (i == BB) p1done_cnt = 0;
    }
    if (i < IND) xs[i] = x[((size_t)b * TT + t) * IND + i];
    __syncthreads();
    float acc = 0.0f;
    #pragma unroll
    for (int kb = 0; kb < IND; kb += 8) {
        float w[8];
        #pragma unroll
        for (int u = 0; u < 8; u++) w[u] = Wx[(kb + u) * DD + i];
        #pragma unroll
        for (int u = 0; u < 8; u++) acc = fmaf(xs[kb + u], w[u], acc);
    }
    pre1_scr[((size_t)b * TT + t) * DD + i] = acc;
}

// ---------------- Fused producer/consumer kernel ----------------
// grid = 148 blocks x 256 threads, 1 block/SM (134KB smem) -> all co-resident.
// blocks 0-31: phase1 producer (batch b = blockIdx.x), bit-exact XLA:CPU path.
// blocks 32-147: phase2 consumers, spin on progress[b].
// tail (all blocks): phase3 after p1done_cnt == 32.
#define FUSED_SMEM_FLOATS (2 * DD * DD + 3 * DD + DD)   // max(producer, consumer) layout
#define FUSED_SMEM_BYTES  (FUSED_SMEM_FLOATS * 4)
#define P2_THRESH 64

__global__ void __launch_bounds__(256, 1)
fused_kernel(const float* __restrict__ h0, const float* __restrict__ Wg,
             const float* __restrict__ Wh, float* __restrict__ out)
{
    extern __shared__ float sm[];
    __shared__ float vs[DD];
    __shared__ float hsh[DD];
    __shared__ int cnt;

    const int tid = threadIdx.x;
    const int bid = blockIdx.x;

    if (bid < NPROD) {
        // ================= PRODUCER: phase 1 =================
        float* Whs = sm;                       // [k][i]
        float* Wgs = Whs + DD * DD;            // [k][i]
        float* hs  = Wgs + DD * DD;            // [128]
        float* as_ = hs + DD;                  // [128]

        const int b = bid;
        const int i = tid;                     // threads 0-127 compute

        for (int idx = tid; idx < DD * DD; idx += 256) {
            Whs[idx] = Wh[idx];
            Wgs[idx] = Wg[idx];
        }
        if (i < DD) hs[i] = h0[b * DD + i];
        __syncthreads();

        const float* p1 = pre1_scr + (size_t)b * TT * DD + i;
        float* yrow = out + OUT_Y + (size_t)b * TT * DD;
        const float SQRT2 = 1.41421356237309515f;

        float preP = (i < DD) ? p1[0] : 0.0f;
        for (int t = 0; t < TT; t++) {
            float nextP = 0.0f;
            float pre = 0.0f, a = 0.0f;
            if (i < DD) {
                nextP = (t + 1 < TT) ? p1[(size_t)(t + 1) * DD] : 0.0f;
                // acc2 = ascending chain h @ Wh
                float acc2 = 0.0f;
                #pragma unroll
                for (int kb = 0; kb < DD; kb += 8) {
                    float w[8], hv[8];
                    #pragma unroll
                    for (int u = 0; u < 8; u++) { w[u] = Whs[(kb + u) * DD + i]; hv[u] = hs[kb + u]; }
                    #pragma unroll
                    for (int u = 0; u < 8; u++) acc2 = fmaf(hv[u], w[u], acc2);
                }
                pre = __fadd_rn(preP, acc2);
                // gelu, jax op order
                float u_ = __fdiv_rn(pre, SQRT2);
                float er = erf_xla_cpu(u_);
                a = __fdiv_rn(__fmul_rn(pre, __fadd_rn(er, 1.0f)), 2.0f);
                as_[i] = a;
            }
            __syncthreads();                   // as ready; hs reads done

            if (i < DD) {
                // acc3 = ascending chain a @ Wgate
                float acc3 = 0.0f;
                #pragma unroll
                for (int kb = 0; kb < DD; kb += 8) {
                    float w[8], av[8];
                    #pragma unroll
                    for (int u = 0; u < 8; u++) { w[u] = Wgs[(kb + u) * DD + i]; av[u] = as_[kb + u]; }
                    #pragma unroll
                    for (int u = 0; u < 8; u++) acc3 = fmaf(av[u], w[u], acc3);
                }
                float g = sigmoid_xla_cpu(acc3);
                float h = hs[i];
                float c = (h - 1.0f) * g * (1.0f - g);
                float hn = __fadd_rn(__fmul_rn(g, h), __fsub_rn(1.0f, g));

                size_t o = ((size_t)t * BB + b) * DD + i;
                g_scr[o] = g;
                c_scr[o] = c;
                p_scr[o] = pre;
                yrow[(size_t)t * DD + i] = hn;
                hs[i] = hn;
                __threadfence();               // make scr writes device-visible
            }
            __syncthreads();                   // hs published; scr visible
            if (tid == 0) progress[b] = t + 1; // release flag
            preP = nextP;
        }

        // h_final + extra eval for dh_dWh
        if (i < DD) out[b * DD + i] = hs[i];
        {
            float pre = 0.0f, a = 0.0f;
            if (i < DD) {
                float acc1 = p1[(size_t)(TT - 1) * DD];
                float acc2 = 0.0f;
                #pragma unroll
                for (int kb = 0; kb < DD; kb += 8) {
                    float w[8], hv[8];
                    #pragma unroll
                    for (int u = 0; u < 8; u++) { w[u] = Whs[(kb + u) * DD + i]; hv[u] = hs[kb + u]; }
                    #pragma unroll
                    for (int u = 0; u < 8; u++) acc2 = fmaf(hv[u], w[u], acc2);
                }
                pre = __fadd_rn(acc1, acc2);
                float u_ = __fdiv_rn(pre, SQRT2);
                float er = erf_xla_cpu(u_);
                a = __fdiv_rn(__fmul_rn(pre, __fadd_rn(er, 1.0f)), 2.0f);
                float cdf = 0.5f * (1.0f + er);
                d2_scr[b * DD + i] = cdf + pre * 0.3989422804014327f * expf(-0.5f * pre * pre);
                as_[i] = a;
            }
            __syncthreads();
            if (i < DD) {
                float acc3 = 0.0f;
                #pragma unroll
                for (int kb = 0; kb < DD; kb += 8) {
                    float w[8], av[8];
                    #pragma unroll
                    for (int u = 0; u < 8; u++) { w[u] = Wgs[(kb + u) * DD + i]; av[u] = as_[kb + u]; }
                    #pragma unroll
                    for (int u = 0; u < 8; u++) acc3 = fmaf(av[u], w[u], acc3);
                }
                float g = sigmoid_xla_cpu(acc3);
                float h = hs[i];
                c2_scr[b * DD + i] = (h - 1.0f) * g * (1.0f - g);
                __threadfence();
            }
        }
        __syncthreads();
        if (tid == 0) atomicAdd(&p1done_cnt, 1);
    } else {
        // ================= CONSUMER: phase 2 =================
        float* Wgs = sm;                 // [k][i]
        float* WhT = sm + DD * DD;       // [k][j] = Wh[j][k]
        float* ds  = WhT + DD * DD;
        float* cs  = ds + DD;
        float* gs  = cs + DD;
        int* rowlist = (int*)(gs + DD);

        for (int idx = tid; idx < DD * DD; idx += 256) Wgs[idx] = Wg[idx];
        for (int idx = tid; idx < DD * DD; idx += 256) {
            int j = idx / DD, k = idx % DD;
            WhT[k * DD + j] = Wh[idx];
        }

        const int ti = tid & 15, tj = tid >> 4;
        const int i0 = ti * 8, j0 = tj * 8;
        float* jbase = out + OUT_JAC;
        const int cid = bid - NPROD;

        for (int job = cid; job < TT * BB; job += NCONS) {
            const int b = job & (BB - 1);
            const int t = job >> 5;
            if (tid == 0) {
                while (progress[b] < t + 1) __nanosleep(64);
                cnt = 0;
            }
            __syncthreads();             // spin done; also protects smem from prev job
            if (tid < DD) {
                size_t o = (size_t)job * DD + tid;
                float pre = __ldcg(&p_scr[o]);
                float cdf = 0.5f * (1.0f + erff(pre * 0.7071067811865476f));
                ds[tid] = cdf + pre * 0.3989422804014327f * expf(-0.5f * pre * pre);
                float c = __ldcg(&c_scr[o]);
                cs[tid] = c;
                gs[tid] = __ldcg(&g_scr[o]);
                if (c != 0.0f) { int p = atomicAdd(&cnt, 1); rowlist[p] = tid; }
            }
            __syncthreads();
            int n = cnt;
            float* jac = jbase + (size_t)job * (DD * DD);

            if (n > P2_THRESH) {
                float acc[8][8];
                #pragma unroll
                for (int a = 0; a < 8; a++)
                    #pragma unroll
                    for (int q = 0; q < 8; q++) acc[a][q] = 0.f;

                #pragma unroll 2
                for (int k = 0; k < DD; k++) {
                    float dk = ds[k];
                    float4 wa0 = *(const float4*)(Wgs + k * DD + i0);
                    float4 wa1 = *(const float4*)(Wgs + k * DD + i0 + 4);
                    float4 wb0 = *(const float4*)(WhT + k * DD + j0);
                    float4 wb1 = *(const float4*)(WhT + k * DD + j0 + 4);
                    float av[8] = {wa0.x * dk, wa0.y * dk, wa0.z * dk, wa0.w * dk,
                                   wa1.x * dk, wa1.y * dk, wa1.z * dk, wa1.w * dk};
                    float bv[8] = {wb0.x, wb0.y, wb0.z, wb0.w, wb1.x, wb1.y, wb1.z, wb1.w};
                    #pragma unroll
                    for (int a = 0; a < 8; a++)
                        #pragma unroll
                        for (int q = 0; q < 8; q++)
                            acc[a][q] = fmaf(av[a], bv[q], acc[a][q]);
                }

                #pragma unroll
                for (int a = 0; a < 8; a++) {
                    int irow = i0 + a;
                    float ci = cs[irow], gi = gs[irow];
                    float v[8];
                    #pragma unroll
                    for (int q = 0; q < 8; q++) {
                        float val = ci * acc[a][q];
                        if (irow == j0 + q) val += gi;
                        v[q] = val;
                    }
                    float* dst = jac + (size_t)irow * DD + j0;
                    *(float4*)(dst)     = make_float4(v[0], v[1], v[2], v[3]);
                    *(float4*)(dst + 4) = make_float4(v[4], v[5], v[6], v[7]);
                }
            } else {
                // inactive rows: exact g_i * e_i
                float4* j4 = (float4*)jac;
                #pragma unroll 4
                for (int idx = tid; idx < DD * DD / 4; idx += 256) {
                    int row = idx >> 5;
                    if (cs[row] == 0.0f) {
                        int c0 = (idx & 31) << 2;
                        float gv = gs[row];
                        float4 v;
                        v.x = (row == c0 + 0) ? gv : 0.f;
                        v.y = (row == c0 + 1) ? gv : 0.f;
                        v.z = (row == c0 + 2) ? gv : 0.f;
                        v.w = (row == c0 + 3) ? gv : 0.f;
                        j4[idx] = v;
                    }
                }
                // active rows: 2 rows per pass
                for (int r = 0; r < n; r += 2) {
                    int rr = r + (tid >> 7);
                    if (rr < n) {
                        int irow = rowlist[rr];
                        int j = tid & 127;
                        float a0 = 0.f, a1 = 0.f;
                        #pragma unroll 4
                        for (int k = 0; k < DD; k += 2) {
                            a0 = fmaf(ds[k]     * Wgs[k * DD + irow],       WhT[k * DD + j],       a0);
                            a1 = fmaf(ds[k + 1] * Wgs[(k + 1) * DD + irow], WhT[(k + 1) * DD + j], a1);
                        }
                        float val = cs[irow] * (a0 + a1);
                        if (irow == j) val += gs[irow];
                        jac[(size_t)irow * DD + j] = val;
                    }
                }
            }
        }
    }

    // ================= TAIL: phase 3 (all blocks) =================
    __syncthreads();
    if (tid == 0) {
        while (*(volatile int*)&p1done_cnt < NPROD) __nanosleep(128);
    }
    __syncthreads();

    for (int bi = bid; bi < BB * DD; bi += NSM) {
        const int b = bi >> 7, i = bi & 127;
        if (tid < DD) {
            float c2 = __ldcg(&c2_scr[b * DD + i]);
            vs[tid]  = c2 * __ldcg(&d2_scr[b * DD + tid]) * Wg[tid * DD + i];
            hsh[tid] = __ldcg(&out[b * DD + tid]);   // h_final
        }
        __syncthreads();
        float4* dst = (float4*)(out + OUT_DWH + (size_t)bi * DD * DD);
        const float4* vs4 = (const float4*)vs;
        #pragma unroll 4
        for (int idx = tid; idx < DD * DD / 4; idx += 256) {
            int p  = idx >> 5;
            int q4 = idx & 31;
            float hp = hsh[p];
            float4 v = vs4[q4];
            dst[idx] = make_float4(v.x * hp, v.y * hp, v.z * hp, v.w * hp);
        }
        __syncthreads();   // protect vs/hsh before next bi
    }
}

extern "C" void kernel_launch(void* const* d_in, const int* in_sizes, int n_in,
                              void* d_out, int out_size) {
    const float* x  = (const float*)d_in[0];
    const float* h0 = (const float*)d_in[1];
    const float* Wx = (const float*)d_in[2];
    const float* Wg = (const float*)d_in[3];
    const float* Wh = (const float*)d_in[4];
    float* out = (float*)d_out;

    cudaFuncSetAttribute(fused_kernel, cudaFuncAttributeMaxDynamicSharedMemorySize, FUSED_SMEM_BYTES);

    dim3 g0(TT, BB);
    phase0_kernel<<<g0, 128>>>(x, Wx);
    fused_kernel<<<NSM, 256, FUSED_SMEM_BYTES>>>(h0, Wg, Wh, out);
}

// round 13
// speedup vs baseline: 3.1133x; 1.2048x over previous
#include <cuda_runtime.h>
#include <math.h>

#define BB 32
#define TT 256
#define IND 64
#define DD 128

#define NSM   148
#define NPROD 32
#define NCONS (NSM - NPROD)

// output layout (floats): h_final | y | jacs | dh_dWh
#define OUT_Y   ((size_t)BB * DD)
#define OUT_JAC (OUT_Y + (size_t)BB * TT * DD)
#define OUT_DWH (OUT_JAC + (size_t)TT * BB * DD * DD)

// scratch (device globals; allocation-free rule)
__device__ float g_scr[TT * BB * DD];
__device__ float c_scr[TT * BB * DD];
__device__ float p_scr[TT * BB * DD];
__device__ float c2_scr[BB * DD];
__device__ float d2_scr[BB * DD];
__device__ volatile int progress[BB];
__device__ int p1done_cnt;

// ---------------- XLA:CPU math replicas (bit-exact path) ----------------
__device__ __forceinline__ float erf_xla_cpu(float x) {
    float w  = fminf(fmaxf(x, -4.0f), 4.0f);
    float x2 = __fmul_rn(w, w);
    float p;
    p = __fadd_rn(__fmul_rn(x2, -2.72614225801306e-10f), 2.77068142495902e-08f);
    p = __fadd_rn(__fmul_rn(x2, p), -2.10102402082508e-06f);
    p = __fadd_rn(__fmul_rn(x2, p), -5.69250639462346e-05f);
    p = __fadd_rn(__fmul_rn(x2, p), -7.34990630326855e-04f);
    p = __fadd_rn(__fmul_rn(x2, p), -2.95459980854025e-03f);
    p = __fadd_rn(__fmul_rn(x2, p), -1.60960333262415e-02f);
    p = __fmul_rn(w, p);
    float q;
    q = __fadd_rn(__fmul_rn(x2, -1.45660718464996e-05f), -2.13374055278905e-04f);
    q = __fadd_rn(__fmul_rn(x2, q), -1.68282697438203e-03f);
    q = __fadd_rn(__fmul_rn(x2, q), -7.37332916720468e-03f);
    q = __fadd_rn(__fmul_rn(x2, q), -1.42647390514189e-02f);
    return __fdiv_rn(p, q);
}

// Fast near-CR f32 exp via f64: 32-entry 2^(j/32) table (glibc exp2f layout,
// exponent folded via 1.5*2^52 shift trick) + fdlibm hi/lo ln2 reduction +
// degree-6 Estrin Taylor. rel err ~2^-51.
__device__ const unsigned long long EXPTAB[32] = {
    0x3ff0000000000000ULL, 0x3fefd9b0d3158574ULL, 0x3fefb5586cf9890fULL, 0x3fef9301d0125b51ULL,
    0x3fef72b83c7d517bULL, 0x3fef54873168b9aaULL, 0x3fef387a6e756238ULL, 0x3fef1e9df51fdee1ULL,
    0x3fef06fe0a31b715ULL, 0x3feef1a7373aa9cbULL, 0x3feedea64c123422ULL, 0x3feece086061892dULL,
    0x3feebfdad5362a27ULL, 0x3feeb42b569d4f82ULL, 0x3feeab07dd485429ULL, 0x3feea47eb03a5585ULL,
    0x3feea09e667f3bcdULL, 0x3fee9f75e8ec5f74ULL, 0x3feea11473eb0187ULL, 0x3feea589994cce13ULL,
    0x3feeace5422aa0dbULL, 0x3feeb737b0cdc5e5ULL, 0x3feec49182a3f090ULL, 0x3feed503b23e255dULL,
    0x3feee89f995ad3adULL, 0x3feeff76f2fb5e47ULL, 0x3fef199bdd85529cULL, 0x3fef3720dcef9069ULL,
    0x3fef5818dcfba487ULL, 0x3fef7c97337b9b5fULL, 0x3fefa4afa2a490daULL, 0x3fefd0765b6e4540ULL
};

__device__ __forceinline__ float exp_cr_fast(float xf) {
    const double Shift = 6755399441055744.0;               // 1.5 * 2^52
    double x = (double)xf;
    double z = __fma_rn(x, 0x1.71547652b82fep+5, Shift);   // x * 32/ln2 + Shift
    unsigned long long kbits = (unsigned long long)__double_as_longlong(z);
    double kd = z - Shift;
    double r  = __fma_rn(kd, -0x1.62e42feep-6, x);         // ln2_hi / 32
    r = __fma_rn(kd, -0x1.a39ef35793c76p-38, r);           // ln2_lo / 32
    unsigned long long tbits = EXPTAB[kbits & 31] + (kbits << 47);
    double s = __longlong_as_double((long long)tbits);
    double r2 = r * r;
    double A  = __fma_rn(r, 0x1.5555555555555p-3, 0.5);
    double B  = __fma_rn(r, 0x1.1111111111111p-7, 0x1.5555555555555p-5);
    double u  = r + 1.0;
    double r4 = r2 * r2;
    double C  = __fma_rn(r2, 0x1.6c16c16c16c17p-10, B);
    double P  = __fma_rn(r2, A, u);
    double e  = __fma_rn(r4, C, P);
    return (float)(e * s);
}

__device__ __forceinline__ float sigmoid_xla_cpu(float s) {
    float e = exp_cr_fast(__fmul_rn(s, -1.0f));
    return __fdiv_rn(1.0f, __fadd_rn(1.0f, e));
}

__global__ void reset_kernel() {
    int i = threadIdx.x;
    if (i < BB) progress[i] = 0;
    if (i == BB) p1done_cnt = 0;
}

#define PROD_SMEM_FLOATS (2 * DD * DD + IND * DD + DD + DD + 2 * IND)
#define CONS_SMEM_FLOATS (2 * DD * DD + 3 * DD + DD)
#define FUSED_SMEM_FLOATS (PROD_SMEM_FLOATS > CONS_SMEM_FLOATS ? PROD_SMEM_FLOATS : CONS_SMEM_FLOATS)
#define FUSED_SMEM_BYTES  (FUSED_SMEM_FLOATS * 4)
#define P2_THRESH 64

__global__ void __launch_bounds__(256, 1)
fused_kernel(const float* __restrict__ x, const float* __restrict__ h0,
             const float* __restrict__ Wx, const float* __restrict__ Wg,
             const float* __restrict__ Wh, float* __restrict__ out)
{
    extern __shared__ float sm[];
    __shared__ float vs[DD];
    __shared__ float hsh[DD];
    __shared__ int cnt;

    const int tid = threadIdx.x;
    const int bid = blockIdx.x;

    if (bid < NPROD) {
        // ================= PRODUCER: phase 1 (bit-exact XLA:CPU) =================
        float* Whs = sm;
        float* Wgs = Whs + DD * DD;
        float* Wxs = Wgs + DD * DD;
        float* hs  = Wxs + IND * DD;
        float* as_ = hs + DD;
        float* xsb = as_ + DD;                 // [2][64]

        const int b = bid;
        const int i = tid;
        const float* xrow = x + (size_t)b * TT * IND;

        for (int idx = tid; idx < DD * DD; idx += 256) {
            Whs[idx] = Wh[idx];
            Wgs[idx] = Wg[idx];
        }
        for (int idx = tid; idx < IND * DD; idx += 256) Wxs[idx] = Wx[idx];
        if (i < IND) xsb[i] = xrow[i];
        if (i < DD) hs[i] = h0[b * DD + i];
        __syncthreads();

        float* yrow = out + OUT_Y + (size_t)b * TT * DD;
        const float SQRT2 = 1.41421356237309515f;

        for (int t = 0; t < TT; t++) {
            const bool pub = ((t & 3) == 3);
            if (tid >= 128 && tid < 128 + IND) {
                int tn = t + 1;
                if (tn < TT) xsb[((tn & 1) << 6) + (tid - 128)] = xrow[(size_t)tn * IND + (tid - 128)];
            }
            if (i < DD) {
                const float* xv = xsb + ((t & 1) << 6);
                float acc1 = 0.0f, acc2 = 0.0f;
                #pragma unroll
                for (int kb = 0; kb < IND; kb += 8) {
                    float wx[8], xr[8], wh[8], hr[8];
                    #pragma unroll
                    for (int u = 0; u < 8; u++) {
                        wx[u] = Wxs[(kb + u) * DD + i]; xr[u] = xv[kb + u];
                        wh[u] = Whs[(kb + u) * DD + i]; hr[u] = hs[kb + u];
                    }
                    #pragma unroll
                    for (int u = 0; u < 8; u++) {
                        acc1 = fmaf(xr[u], wx[u], acc1);
                        acc2 = fmaf(hr[u], wh[u], acc2);
                    }
                }
                #pragma unroll
                for (int kb = IND; kb < DD; kb += 8) {
                    float wh[8], hr[8];
                    #pragma unroll
                    for (int u = 0; u < 8; u++) { wh[u] = Whs[(kb + u) * DD + i]; hr[u] = hs[kb + u]; }
                    #pragma unroll
                    for (int u = 0; u < 8; u++) acc2 = fmaf(hr[u], wh[u], acc2);
                }
                float pre = __fadd_rn(acc1, acc2);
                float u_ = __fdiv_rn(pre, SQRT2);
                float er = erf_xla_cpu(u_);
                float a  = __fmul_rn(__fmul_rn(pre, __fadd_rn(er, 1.0f)), 0.5f);
                as_[i] = a;
                p_scr[((size_t)t * BB + b) * DD + i] = pre;
            }
            __syncthreads();

            if (i < DD) {
                float acc3 = 0.0f;
                #pragma unroll
                for (int kb = 0; kb < DD; kb += 8) {
                    float w[8], av[8];
                    #pragma unroll
                    for (int u = 0; u < 8; u++) { w[u] = Wgs[(kb + u) * DD + i]; av[u] = as_[kb + u]; }
                    #pragma unroll
                    for (int u = 0; u < 8; u++) acc3 = fmaf(av[u], w[u], acc3);
                }
                float g = sigmoid_xla_cpu(acc3);
                float h = hs[i];
                float c = (h - 1.0f) * g * (1.0f - g);
                float hn = __fadd_rn(__fmul_rn(g, h), __fsub_rn(1.0f, g));

                size_t o = ((size_t)t * BB + b) * DD + i;
                g_scr[o] = g;
                c_scr[o] = c;
                yrow[(size_t)t * DD + i] = hn;
                hs[i] = hn;
                if (pub) __threadfence();
            }
            __syncthreads();
            if (pub && tid == 0) progress[b] = t + 1;
        }

        if (i < DD) out[b * DD + i] = hs[i];
        {
            if (i < DD) {
                const float* xv = xsb + (((TT - 1) & 1) << 6);
                float acc1 = 0.0f, acc2 = 0.0f;
                #pragma unroll
                for (int kb = 0; kb < IND; kb += 8) {
                    float wx[8], xr[8], wh[8], hr[8];
                    #pragma unroll
                    for (int u = 0; u < 8; u++) {
                        wx[u] = Wxs[(kb + u) * DD + i]; xr[u] = xv[kb + u];
                        wh[u] = Whs[(kb + u) * DD + i]; hr[u] = hs[kb + u];
                    }
                    #pragma unroll
                    for (int u = 0; u < 8; u++) {
                        acc1 = fmaf(xr[u], wx[u], acc1);
                        acc2 = fmaf(hr[u], wh[u], acc2);
                    }
                }
                #pragma unroll
                for (int kb = IND; kb < DD; kb += 8) {
                    float wh[8], hr[8];
                    #pragma unroll
                    for (int u = 0; u < 8; u++) { wh[u] = Whs[(kb + u) * DD + i]; hr[u] = hs[kb + u]; }
                    #pragma unroll
                    for (int u = 0; u < 8; u++) acc2 = fmaf(hr[u], wh[u], acc2);
                }
                float pre = __fadd_rn(acc1, acc2);
                float u_ = __fdiv_rn(pre, SQRT2);
                float er = erf_xla_cpu(u_);
                float a  = __fmul_rn(__fmul_rn(pre, __fadd_rn(er, 1.0f)), 0.5f);
                float cdf = 0.5f * (1.0f + er);
                d2_scr[b * DD + i] = cdf + pre * 0.3989422804014327f * expf(-0.5f * pre * pre);
                as_[i] = a;
            }
            __syncthreads();
            if (i < DD) {
                float acc3 = 0.0f;
                #pragma unroll
                for (int kb = 0; kb < DD; kb += 8) {
                    float w[8], av[8];
                    #pragma unroll
                    for (int u = 0; u < 8; u++) { w[u] = Wgs[(kb + u) * DD + i]; av[u] = as_[kb + u]; }
                    #pragma unroll
                    for (int u = 0; u < 8; u++) acc3 = fmaf(av[u], w[u], acc3);
                }
                float g = sigmoid_xla_cpu(acc3);
                float h = hs[i];
                c2_scr[b * DD + i] = (h - 1.0f) * g * (1.0f - g);
                __threadfence();
            }
        }
        __syncthreads();
        if (tid == 0) atomicAdd(&p1done_cnt, 1);
    } else {
        // ================= CONSUMER: phase 2 =================
        float* Wgs = sm;
        float* WhT = sm + DD * DD;
        float* ds  = WhT + DD * DD;
        float* cs  = ds + DD;
        float* gs  = cs + DD;
        int* rowlist = (int*)(gs + DD);

        for (int idx = tid; idx < DD * DD; idx += 256) Wgs[idx] = Wg[idx];
        for (int idx = tid; idx < DD * DD; idx += 256) {
            int j = idx / DD, k = idx % DD;
            WhT[k * DD + j] = Wh[idx];
        }

        const int ti = tid & 15, tj = tid >> 4;
        const int i0 = ti * 8, j0 = tj * 8;
        float* jbase = out + OUT_JAC;
        const int cid = bid - NPROD;

        for (int job = cid; job < TT * BB; job += NCONS) {
            const int b = job & (BB - 1);
            const int t = job >> 5;
            if (tid == 0) {
                while (progress[b] < t + 1) __nanosleep(64);
                __threadfence();
                cnt = 0;
            }
            __syncthreads();
            if (tid < DD) {
                size_t o = (size_t)job * DD + tid;
                float pre = __ldcg(&p_scr[o]);
                float cdf = 0.5f * (1.0f + erff(pre * 0.7071067811865476f));
                ds[tid] = cdf + pre * 0.3989422804014327f * expf(-0.5f * pre * pre);
                float c = __ldcg(&c_scr[o]);
                cs[tid] = c;
                gs[tid] = __ldcg(&g_scr[o]);
                if (c != 0.0f) { int p = atomicAdd(&cnt, 1); rowlist[p] = tid; }
            }
            __syncthreads();
            int n = cnt;
            float* jac = jbase + (size_t)job * (DD * DD);

            if (n > P2_THRESH) {
                float acc[8][8];
                #pragma unroll
                for (int a = 0; a < 8; a++)
                    #pragma unroll
                    for (int q = 0; q < 8; q++) acc[a][q] = 0.f;

                #pragma unroll 2
                for (int k = 0; k < DD; k++) {
                    float dk = ds[k];
                    float4 wa0 = *(const float4*)(Wgs + k * DD + i0);
                    float4 wa1 = *(const float4*)(Wgs + k * DD + i0 + 4);
                    float4 wb0 = *(const float4*)(WhT + k * DD + j0);
                    float4 wb1 = *(const float4*)(WhT + k * DD + j0 + 4);
                    float av[8] = {wa0.x * dk, wa0.y * dk, wa0.z * dk, wa0.w * dk,
                                   wa1.x * dk, wa1.y * dk, wa1.z * dk, wa1.w * dk};
                    float bv[8] = {wb0.x, wb0.y, wb0.z, wb0.w, wb1.x, wb1.y, wb1.z, wb1.w};
                    #pragma unroll
                    for (int a = 0; a < 8; a++)
                        #pragma unroll
                        for (int q = 0; q < 8; q++)
                            acc[a][q] = fmaf(av[a], bv[q], acc[a][q]);
                }

                #pragma unroll
                for (int a = 0; a < 8; a++) {
                    int irow = i0 + a;
                    float ci = cs[irow], gi = gs[irow];
                    float v[8];
                    #pragma unroll
                    for (int q = 0; q < 8; q++) {
                        float val = ci * acc[a][q];
                        if (irow == j0 + q) val += gi;
                        v[q] = val;
                    }
                    float* dst = jac + (size_t)irow * DD + j0;
                    *(float4*)(dst)     = make_float4(v[0], v[1], v[2], v[3]);
                    *(float4*)(dst + 4) = make_float4(v[4], v[5], v[6], v[7]);
                }
            } else {
                float4* j4 = (float4*)jac;
                #pragma unroll 4
                for (int idx = tid; idx < DD * DD / 4; idx += 256) {
                    int row = idx >> 5;
                    if (cs[row] == 0.0f) {
                        int c0 = (idx & 31) << 2;
                        float gv = gs[row];
                        float4 v;
                        v.x = (row == c0 + 0) ? gv : 0.f;
                        v.y = (row == c0 + 1) ? gv : 0.f;
                        v.z = (row == c0 + 2) ? gv : 0.f;
                        v.w = (row == c0 + 3) ? gv : 0.f;
                        j4[idx] = v;
                    }
                }
                for (int r = 0; r < n; r += 2) {
                    int rr = r + (tid >> 7);
                    if (rr < n) {
                        int irow = rowlist[rr];
                        int j = tid & 127;
                        float a0 = 0.f, a1 = 0.f;
                        #pragma unroll 4
                        for (int k = 0; k < DD; k += 2) {
                            a0 = fmaf(ds[k]     * Wgs[k * DD + irow],       WhT[k * DD + j],       a0);
                            a1 = fmaf(ds[k + 1] * Wgs[(k + 1) * DD + irow], WhT[(k + 1) * DD + j], a1);
                        }
                        float val = cs[irow] * (a0 + a1);
                        if (irow == j) val += gs[irow];
                        jac[(size_t)irow * DD + j] = val;
                    }
                }
            }
        }
    }

    // ================= TAIL: phase 3 (all blocks) =================
    __syncthreads();
    if (tid == 0) {
        while (*(volatile int*)&p1done_cnt < NPROD) __nanosleep(128);
        __threadfence();
    }
    __syncthreads();

    for (int bi = bid; bi < BB * DD; bi += NSM) {
        const int b = bi >> 7, i = bi & 127;
        if (tid < DD) {
            float c2 = __ldcg(&c2_scr[b * DD + i]);
            vs[tid]  = c2 * __ldcg(&d2_scr[b * DD + tid]) * Wg[tid * DD + i];
            hsh[tid] = __ldcg(&out[b * DD + tid]);
        }
        __syncthreads();
        float4* dst = (float4*)(out + OUT_DWH + (size_t)bi * DD * DD);
        const float4* vs4 = (const float4*)vs;
        #pragma unroll 4
        for (int idx = tid; idx < DD * DD / 4; idx += 256) {
            int p  = idx >> 5;
            int q4 = idx & 31;
            float hp = hsh[p];
            float4 v = vs4[q4];
            dst[idx] = make_float4(v.x * hp, v.y * hp, v.z * hp, v.w * hp);
        }
        __syncthreads();
    }
}

extern "C" void kernel_launch(void* const* d_in, const int* in_sizes, int n_in,
                              void* d_out, int out_size) {
    const float* x  = (const float*)d_in[0];
    const float* h0 = (const float*)d_in[1];
    const float* Wx = (const float*)d_in[2];
    const float* Wg = (const float*)d_in[3];
    const float* Wh = (const float*)d_in[4];
    float* out = (float*)d_out;

    cudaFuncSetAttribute(fused_kernel, cudaFuncAttributeMaxDynamicSharedMemorySize, FUSED_SMEM_BYTES);

    reset_kernel<<<1, 64>>>();
    fused_kernel<<<NSM, 256, FUSED_SMEM_BYTES>>>(x, h0, Wx, Wg, Wh, out);
}